// round 1
// baseline (speedup 1.0000x reference)
#include <cuda_runtime.h>
#include <cstdint>

// Problem constants (fixed shapes)
#define NODES 32768       // B*N
#define NPB   16384       // nodes per batch
#define FDIM  64          // node feature dim (F)
#define EDIM  16          // edge feature dim (E)
#define KNB   32          // neighbors per node (K)
#define KDIM  1024        // F*E, GEMM reduction dim

// Scratch (allocation-free rule: __device__ globals)
__device__ float g_T[(size_t)NODES * KDIM];      // 128 MB: T[node][l*16+n]
__device__ float g_Wd[KDIM * 2 * FDIM];          // 512 KB: W' duplicated pairs

typedef unsigned long long u64;

__device__ __forceinline__ u64 pack2(float lo, float hi) {
    u64 r; asm("mov.b64 %0, {%1, %2};" : "=l"(r) : "f"(lo), "f"(hi)); return r;
}
__device__ __forceinline__ void unpack2(u64 v, float& lo, float& hi) {
    asm("mov.b64 {%0, %1}, %2;" : "=f"(lo), "=f"(hi) : "l"(v));
}
__device__ __forceinline__ u64 ffma2(u64 a, u64 b, u64 c) {
    u64 d; asm("fma.rn.f32x2 %0, %1, %2, %3;" : "=l"(d) : "l"(a), "l"(b), "l"(c)); return d;
}
__device__ __forceinline__ u64 fmul2(u64 a, u64 b) {
    u64 d; asm("mul.rn.f32x2 %0, %1, %2;" : "=l"(d) : "l"(a), "l"(b)); return d;
}

// ---------------------------------------------------------------------------
// Kernel 0: permute w[l][m][n] -> W'[k=(l*16+n)][m], stored DUPLICATED:
// g_Wd[k][2m] = g_Wd[k][2m+1] = w[l,m,n]. Duplication makes GEMM B-operands
// directly loadable as f32x2 broadcast pairs (no per-k register packing).
// ---------------------------------------------------------------------------
__global__ __launch_bounds__(256) void perm_w_kernel(const float* __restrict__ w) {
    int idx = blockIdx.x * blockDim.x + threadIdx.x;   // 0..65535
    int k = idx >> 6;          // 0..1023
    int m = idx & 63;
    int l = k >> 4;
    int n = k & 15;
    float v = w[l * (FDIM * EDIM) + m * EDIM + n];
    g_Wd[k * (2 * FDIM) + 2 * m]     = v;
    g_Wd[k * (2 * FDIM) + 2 * m + 1] = v;
}

// ---------------------------------------------------------------------------
// Kernel 1: stage 1 — gather neighbors + rank-32 outer product per node.
// One warp per node. Lane owns l = {2*lane, 2*lane+1}, all n (32 T values,
// kept as 16 packed f32x2 accumulators paired over n).
// ---------------------------------------------------------------------------
__global__ __launch_bounds__(256) void stage1_kernel(
    const float* __restrict__ nodes,
    const int*   __restrict__ nlist,
    const float* __restrict__ edges)
{
    __shared__ float se[8][512];       // per-warp edge tile (K*E floats)

    const int warp = threadIdx.x >> 5;
    const int lane = threadIdx.x & 31;
    const int node = (blockIdx.x << 3) + warp;          // 8 warps/block
    const int b    = node >> 14;
    const float* nbase = nodes + (size_t)b * NPB * FDIM;

    // cooperative edge load: 512 floats = 128 float4, 4 per lane (coalesced)
    const float4* e4 = (const float4*)(edges + (size_t)node * (KNB * EDIM));
    float4* s4 = (float4*)se[warp];
    s4[lane]       = e4[lane];
    s4[lane + 32]  = e4[lane + 32];
    s4[lane + 64]  = e4[lane + 64];
    s4[lane + 96]  = e4[lane + 96];
    int idx = nlist[node * KNB + lane];                 // lane j holds nlist[j]
    __syncwarp();

    u64 T0[8], T1[8];                  // T0: l=2*lane, T1: l=2*lane+1; pairs over n
#pragma unroll
    for (int p = 0; p < 8; ++p) { T0[p] = 0ull; T1[p] = 0ull; }

    // software-pipelined gather: prefetch next neighbor row while FMAing current
    int nb = __shfl_sync(0xffffffffu, idx, 0);
    float2 x = *(const float2*)(nbase + (size_t)nb * FDIM + 2 * lane);

#pragma unroll
    for (int j = 0; j < KNB; ++j) {
        float2 xc = x;
        if (j + 1 < KNB) {
            nb = __shfl_sync(0xffffffffu, idx, j + 1);
            x  = *(const float2*)(nbase + (size_t)nb * FDIM + 2 * lane);
        }
        u64 xx0 = pack2(xc.x, xc.x);
        u64 xx1 = pack2(xc.y, xc.y);
        // e pairs straight from smem as LDS.128 (broadcast across lanes)
        const ulonglong2* ep = (const ulonglong2*)&se[warp][j * EDIM];
        ulonglong2 e01 = ep[0];
        ulonglong2 e23 = ep[1];
        ulonglong2 e45 = ep[2];
        ulonglong2 e67 = ep[3];
        T0[0] = ffma2(xx0, e01.x, T0[0]);  T0[1] = ffma2(xx0, e01.y, T0[1]);
        T0[2] = ffma2(xx0, e23.x, T0[2]);  T0[3] = ffma2(xx0, e23.y, T0[3]);
        T0[4] = ffma2(xx0, e45.x, T0[4]);  T0[5] = ffma2(xx0, e45.y, T0[5]);
        T0[6] = ffma2(xx0, e67.x, T0[6]);  T0[7] = ffma2(xx0, e67.y, T0[7]);
        T1[0] = ffma2(xx1, e01.x, T1[0]);  T1[1] = ffma2(xx1, e01.y, T1[1]);
        T1[2] = ffma2(xx1, e23.x, T1[2]);  T1[3] = ffma2(xx1, e23.y, T1[3]);
        T1[4] = ffma2(xx1, e45.x, T1[4]);  T1[5] = ffma2(xx1, e45.y, T1[5]);
        T1[6] = ffma2(xx1, e67.x, T1[6]);  T1[7] = ffma2(xx1, e67.y, T1[7]);
    }

    // scale by 1/K and store lane's contiguous 32 floats: k in [32*lane, 32*lane+32)
    const u64 sc = pack2(0.03125f, 0.03125f);
    ulonglong2* tp = (ulonglong2*)(g_T + (size_t)node * KDIM + lane * 32);
#pragma unroll
    for (int p = 0; p < 4; ++p)
        tp[p]     = make_ulonglong2(fmul2(T0[2*p], sc), fmul2(T0[2*p+1], sc));
#pragma unroll
    for (int p = 0; p < 4; ++p)
        tp[4 + p] = make_ulonglong2(fmul2(T1[2*p], sc), fmul2(T1[2*p+1], sc));
}

// ---------------------------------------------------------------------------
// Kernel 2: GEMM  out[32768,64] = g_T[32768,1024] @ W'[1024,64]
// BM=128, BN=64 (full), BK=32. 256 threads, 8x4 micro-tile per thread,
// all-f32x2 inner loop: 16 FFMA2 + 4 LDS.128 per k.
// ---------------------------------------------------------------------------
#define BM 128
#define BK 32

__global__ __launch_bounds__(256) void gemm_kernel(float* __restrict__ out)
{
    __shared__ float As[BK][BM + 4];           // k-major, padded
    __shared__ float Bd[BK][2 * FDIM + 8];     // duplicated pairs, padded

    const int tid = threadIdx.x;
    const int tx  = tid & 15;     // 16 col-groups * 4 cols
    const int ty  = tid >> 4;     // 16 row-groups * 8 rows
    const int blockRow = blockIdx.x * BM;

    u64 acc[4][4];                // [row-pair][col], packed over adjacent rows
#pragma unroll
    for (int p = 0; p < 4; ++p)
#pragma unroll
        for (int c = 0; c < 4; ++c) acc[p][c] = 0ull;

    for (int kt = 0; kt < KDIM / BK; ++kt) {
        const int k0 = kt * BK;
        // A tile: 128 rows x 32 k, transpose on store (coalesced gmem read)
#pragma unroll
        for (int u = 0; u < 4; ++u) {
            int id  = tid + (u << 8);
            int row = id >> 3;
            int c4  = (id & 7) << 2;
            float4 v = *(const float4*)(g_T + (size_t)(blockRow + row) * KDIM + k0 + c4);
            As[c4 + 0][row] = v.x;
            As[c4 + 1][row] = v.y;
            As[c4 + 2][row] = v.z;
            As[c4 + 3][row] = v.w;
        }
        // B tile: pre-duplicated, straight float4 copy
#pragma unroll
        for (int u = 0; u < 4; ++u) {
            int id  = tid + (u << 8);
            int row = id >> 5;
            int c   = (id & 31) << 2;
            *(float4*)&Bd[row][c] = *(const float4*)(g_Wd + (k0 + row) * (2 * FDIM) + c);
        }
        __syncthreads();

#pragma unroll
        for (int kk = 0; kk < BK; ++kk) {
            ulonglong2 a0 = *(const ulonglong2*)&As[kk][ty * 8];       // rows 0-1, 2-3
            ulonglong2 a1 = *(const ulonglong2*)&As[kk][ty * 8 + 4];   // rows 4-5, 6-7
            ulonglong2 b0 = *(const ulonglong2*)&Bd[kk][tx * 8];       // dup m0, m1
            ulonglong2 b1 = *(const ulonglong2*)&Bd[kk][tx * 8 + 4];   // dup m2, m3
            acc[0][0] = ffma2(a0.x, b0.x, acc[0][0]);
            acc[0][1] = ffma2(a0.x, b0.y, acc[0][1]);
            acc[0][2] = ffma2(a0.x, b1.x, acc[0][2]);
            acc[0][3] = ffma2(a0.x, b1.y, acc[0][3]);
            acc[1][0] = ffma2(a0.y, b0.x, acc[1][0]);
            acc[1][1] = ffma2(a0.y, b0.y, acc[1][1]);
            acc[1][2] = ffma2(a0.y, b1.x, acc[1][2]);
            acc[1][3] = ffma2(a0.y, b1.y, acc[1][3]);
            acc[2][0] = ffma2(a1.x, b0.x, acc[2][0]);
            acc[2][1] = ffma2(a1.x, b0.y, acc[2][1]);
            acc[2][2] = ffma2(a1.x, b1.x, acc[2][2]);
            acc[2][3] = ffma2(a1.x, b1.y, acc[2][3]);
            acc[3][0] = ffma2(a1.y, b0.x, acc[3][0]);
            acc[3][1] = ffma2(a1.y, b0.y, acc[3][1]);
            acc[3][2] = ffma2(a1.y, b1.x, acc[3][2]);
            acc[3][3] = ffma2(a1.y, b1.y, acc[3][3]);
        }
        __syncthreads();
    }

    // epilogue: unpack row pairs, vectorized stores
#pragma unroll
    for (int p = 0; p < 4; ++p) {
        float4 vlo, vhi;
        unpack2(acc[p][0], vlo.x, vhi.x);
        unpack2(acc[p][1], vlo.y, vhi.y);
        unpack2(acc[p][2], vlo.z, vhi.z);
        unpack2(acc[p][3], vlo.w, vhi.w);
        int row = blockRow + ty * 8 + 2 * p;
        *(float4*)(out + (size_t)row * FDIM + tx * 4)       = vlo;
        *(float4*)(out + (size_t)(row + 1) * FDIM + tx * 4) = vhi;
    }
}

// ---------------------------------------------------------------------------
extern "C" void kernel_launch(void* const* d_in, const int* in_sizes, int n_in,
                              void* d_out, int out_size) {
    const float* nodes = (const float*)d_in[0];   // [2,16384,64] f32
    const int*   nlist = (const int*)  d_in[1];   // [2,16384,32] i32
    const float* edges = (const float*)d_in[2];   // [2,16384,32,16] f32
    const float* w     = (const float*)d_in[3];   // [64,64,16] f32
    float* out = (float*)d_out;                   // [2,16384,64] f32

    perm_w_kernel<<<(KDIM * FDIM) / 256, 256>>>(w);
    stage1_kernel<<<NODES / 8, 256>>>(nodes, nlist, edges);
    gemm_kernel<<<NODES / BM, 256>>>(out);
}

// round 3
// speedup vs baseline: 1.4822x; 1.4822x over previous
#include <cuda_runtime.h>
#include <cstdint>

// Problem constants (fixed shapes)
#define NODES 32768       // B*N
#define NPB   16384       // nodes per batch
#define FDIM  64          // node feature dim (F)
#define EDIM  16          // edge feature dim (E)
#define KNB   32          // neighbors per node (K)
#define KDIM  1024        // F*E, GEMM reduction dim
#define KCH   32          // GEMM k-chunk

// Scratch (allocation-free rule: __device__ globals)
__device__ __align__(128) float g_T[(size_t)NODES * KDIM];   // 128 MB: T[node][k=l*16+n]
__device__ __align__(128) float g_Whi[KDIM * FDIM];          // 256 KB: W' hi split, [k][m]
__device__ __align__(128) float g_Wlo[KDIM * FDIM];          // 256 KB: W' lo split, [k][m]

typedef unsigned long long u64;

// ---------------- f32x2 helpers (stage 1) ----------------
__device__ __forceinline__ u64 pack2(float lo, float hi) {
    u64 r; asm("mov.b64 %0, {%1, %2};" : "=l"(r) : "f"(lo), "f"(hi)); return r;
}
__device__ __forceinline__ u64 ffma2(u64 a, u64 b, u64 c) {
    u64 d; asm("fma.rn.f32x2 %0, %1, %2, %3;" : "=l"(d) : "l"(a), "l"(b), "l"(c)); return d;
}

// ---------------- tf32 helpers ----------------
__device__ __forceinline__ uint32_t f2tf32(float x) {
    uint32_t r; asm("cvt.rna.tf32.f32 %0, %1;" : "=r"(r) : "f"(x)); return r;
}
__device__ __forceinline__ uint32_t smem_u32(const void* p) {
    uint32_t a;
    asm("{ .reg .u64 t; cvta.to.shared.u64 t, %1; cvt.u32.u64 %0, t; }" : "=r"(a) : "l"(p));
    return a;
}
__device__ __forceinline__ void cp_async16(uint32_t dst, const void* src) {
    asm volatile("cp.async.ca.shared.global [%0], [%1], 16;" :: "r"(dst), "l"(src) : "memory");
}
__device__ __forceinline__ void cp_commit() {
    asm volatile("cp.async.commit_group;" ::: "memory");
}
__device__ __forceinline__ void cp_wait0() {
    asm volatile("cp.async.wait_group 0;" ::: "memory");
}
// m16n8k8 tf32 mma, accumulate in place
__device__ __forceinline__ void mma8(float* c,
                                     uint32_t a0, uint32_t a1, uint32_t a2, uint32_t a3,
                                     uint32_t b0, uint32_t b1) {
    asm volatile(
        "mma.sync.aligned.m16n8k8.row.col.f32.tf32.tf32.f32 "
        "{%0,%1,%2,%3}, {%4,%5,%6,%7}, {%8,%9}, {%0,%1,%2,%3};"
        : "+f"(c[0]), "+f"(c[1]), "+f"(c[2]), "+f"(c[3])
        : "r"(a0), "r"(a1), "r"(a2), "r"(a3), "r"(b0), "r"(b1));
}

// ---------------------------------------------------------------------------
// Kernel 0: permute + scale(1/K) + tf32-split  w[l][m][n] -> Whi/Wlo[k=l*16+n][m]
// ---------------------------------------------------------------------------
__global__ __launch_bounds__(256) void perm_w_kernel(const float* __restrict__ w) {
    int idx = blockIdx.x * blockDim.x + threadIdx.x;   // 0..65535
    int k = idx >> 6;          // 0..1023
    int m = idx & 63;
    int l = k >> 4;
    int n = k & 15;
    float v  = w[l * (FDIM * EDIM) + m * EDIM + n] * 0.03125f;   // fold mean(1/K)
    float hi = __uint_as_float(f2tf32(v));
    float lo = v - hi;
    g_Whi[k * FDIM + m] = hi;
    g_Wlo[k * FDIM + m] = lo;    // kept fp32; converted to tf32 at frag time? no:
    // store lo pre-rounded to tf32 so GEMM can use bits directly
}

__global__ __launch_bounds__(256) void round_wlo_kernel() {
    int idx = blockIdx.x * blockDim.x + threadIdx.x;
    g_Wlo[idx] = __uint_as_float(f2tf32(g_Wlo[idx]));
}

// ---------------------------------------------------------------------------
// Kernel 1: stage 1 — gather neighbors + rank-32 outer product per node.
// One warp per node; depth-8 software pipeline on the gather.
// ---------------------------------------------------------------------------
__global__ __launch_bounds__(256) void stage1_kernel(
    const float* __restrict__ nodes,
    const int*   __restrict__ nlist,
    const float* __restrict__ edges)
{
    __shared__ float se[8][512];       // per-warp edge tile (K*E floats)

    const int warp = threadIdx.x >> 5;
    const int lane = threadIdx.x & 31;
    const int node = (blockIdx.x << 3) + warp;          // 8 warps/block
    const int b    = node >> 14;
    const float* nbase = nodes + (size_t)b * NPB * FDIM;

    const float4* e4 = (const float4*)(edges + (size_t)node * (KNB * EDIM));
    float4* s4 = (float4*)se[warp];
    s4[lane]       = e4[lane];
    s4[lane + 32]  = e4[lane + 32];
    s4[lane + 64]  = e4[lane + 64];
    s4[lane + 96]  = e4[lane + 96];
    int idx = nlist[node * KNB + lane];
    __syncwarp();

    u64 T0[8], T1[8];
#pragma unroll
    for (int p = 0; p < 8; ++p) { T0[p] = 0ull; T1[p] = 0ull; }

    // depth-8 gather pipeline (~256+ cycles of latency tolerance)
    float2 xq[8];
#pragma unroll
    for (int j = 0; j < 8; ++j) {
        int nb = __shfl_sync(0xffffffffu, idx, j);
        xq[j] = *(const float2*)(nbase + (size_t)nb * FDIM + 2 * lane);
    }

#pragma unroll
    for (int j = 0; j < KNB; ++j) {
        float2 xc = xq[j & 7];
        if (j + 8 < KNB) {
            int nb = __shfl_sync(0xffffffffu, idx, j + 8);
            xq[j & 7] = *(const float2*)(nbase + (size_t)nb * FDIM + 2 * lane);
        }
        u64 xx0 = pack2(xc.x, xc.x);
        u64 xx1 = pack2(xc.y, xc.y);
        const ulonglong2* ep = (const ulonglong2*)&se[warp][j * EDIM];
        ulonglong2 e01 = ep[0];
        ulonglong2 e23 = ep[1];
        ulonglong2 e45 = ep[2];
        ulonglong2 e67 = ep[3];
        T0[0] = ffma2(xx0, e01.x, T0[0]);  T0[1] = ffma2(xx0, e01.y, T0[1]);
        T0[2] = ffma2(xx0, e23.x, T0[2]);  T0[3] = ffma2(xx0, e23.y, T0[3]);
        T0[4] = ffma2(xx0, e45.x, T0[4]);  T0[5] = ffma2(xx0, e45.y, T0[5]);
        T0[6] = ffma2(xx0, e67.x, T0[6]);  T0[7] = ffma2(xx0, e67.y, T0[7]);
        T1[0] = ffma2(xx1, e01.x, T1[0]);  T1[1] = ffma2(xx1, e01.y, T1[1]);
        T1[2] = ffma2(xx1, e23.x, T1[2]);  T1[3] = ffma2(xx1, e23.y, T1[3]);
        T1[4] = ffma2(xx1, e45.x, T1[4]);  T1[5] = ffma2(xx1, e45.y, T1[5]);
        T1[6] = ffma2(xx1, e67.x, T1[6]);  T1[7] = ffma2(xx1, e67.y, T1[7]);
    }

    // store lane's contiguous 32 floats: k in [32*lane, 32*lane+32)  (1/K folded into W)
    ulonglong2* tp = (ulonglong2*)(g_T + (size_t)node * KDIM + lane * 32);
#pragma unroll
    for (int p = 0; p < 4; ++p) tp[p]     = make_ulonglong2(T0[2*p], T0[2*p+1]);
#pragma unroll
    for (int p = 0; p < 4; ++p) tp[4 + p] = make_ulonglong2(T1[2*p], T1[2*p+1]);
}

// ---------------------------------------------------------------------------
// Kernel 2: tf32 mma.sync GEMM with 3-split fp32 emulation.
// out[32768,64] = g_T[32768,1024] @ W'[1024,64]
// CTA: 128 rows x 64 cols, 8 warps (warp tile 32x32 = 2 m-tiles x 4 n-tiles).
// A (T) from global into fragments; B (W hi/lo) cp.async double-buffered.
// ---------------------------------------------------------------------------
__global__ __launch_bounds__(256, 2) void gemm_mma_kernel(float* __restrict__ out)
{
    // [buf][split][k(32)][n(64)+8 pad] — bank(8k+n) bijective per warp frag load
    __shared__ __align__(16) float Bs[2][2][KCH][72];

    const int tid  = threadIdx.x;
    const int lane = tid & 31;
    const int wid  = tid >> 5;
    const int tig  = lane & 3;      // thread-in-group (k / col selector)
    const int grp  = lane >> 2;     // group id 0..7 (row / n selector)
    const int mgrp = wid & 3;       // 4 m-groups of 32 rows
    const int ngrp = wid >> 2;      // 2 n-groups of 32 cols
    const int rbase = blockIdx.x * 128 + mgrp * 32;
    const int cbase = ngrp * 32;

    // per-thread A row pointer (row = rbase + grp, col = tig)
    const float* pA = g_T + (size_t)(rbase + grp) * KDIM + tig;

    // B chunk staging: 1024 float4 per chunk, 4 cp.async per thread
    const int s_s  = tid >> 7;          // split
    const int s_i  = tid & 127;
    const int s_k  = s_i >> 2;          // k row 0..31
    const int s_f4 = s_i & 3;           // base float4 col
    const float* s_src = (s_s ? g_Wlo : g_Whi) + (size_t)s_k * FDIM + s_f4 * 4;

    float acc[2][4][4];
#pragma unroll
    for (int mt = 0; mt < 2; ++mt)
#pragma unroll
        for (int nt = 0; nt < 4; ++nt)
#pragma unroll
            for (int r = 0; r < 4; ++r) acc[mt][nt][r] = 0.0f;

    // prologue: stage chunk 0
    {
        uint32_t dst = smem_u32(&Bs[0][s_s][s_k][s_f4 * 4]);
#pragma unroll
        for (int t = 0; t < 4; ++t)
            cp_async16(dst + t * 64, s_src + t * 16);
        cp_commit();
    }

    for (int c = 0; c < KDIM / KCH; ++c) {
        const int b = c & 1;
        cp_wait0();
        __syncthreads();
        if (c + 1 < KDIM / KCH) {
            uint32_t dst = smem_u32(&Bs[b ^ 1][s_s][s_k][s_f4 * 4]);
            const float* src = s_src + (size_t)(c + 1) * KCH * FDIM;
#pragma unroll
            for (int t = 0; t < 4; ++t)
                cp_async16(dst + t * 64, src + t * 16);
            cp_commit();
        }

#pragma unroll
        for (int q = 0; q < 4; ++q) {
            const int offs = c * KCH + q * 8;
            // A raw loads + tf32 split (2 m-tiles)
            uint32_t ah[2][4], al[2][4];
#pragma unroll
            for (int mt = 0; mt < 2; ++mt) {
                const float* p = pA + mt * (16 * KDIM);
                float r0 = p[offs];
                float r1 = p[8 * KDIM + offs];
                float r2 = p[offs + 4];
                float r3 = p[8 * KDIM + offs + 4];
                ah[mt][0] = f2tf32(r0); al[mt][0] = f2tf32(r0 - __uint_as_float(ah[mt][0]));
                ah[mt][1] = f2tf32(r1); al[mt][1] = f2tf32(r1 - __uint_as_float(ah[mt][1]));
                ah[mt][2] = f2tf32(r2); al[mt][2] = f2tf32(r2 - __uint_as_float(ah[mt][2]));
                ah[mt][3] = f2tf32(r3); al[mt][3] = f2tf32(r3 - __uint_as_float(ah[mt][3]));
            }
#pragma unroll
            for (int nt = 0; nt < 4; ++nt) {
                const int n = cbase + nt * 8 + grp;
                uint32_t bh0 = __float_as_uint(Bs[b][0][q * 8 + tig][n]);
                uint32_t bh1 = __float_as_uint(Bs[b][0][q * 8 + tig + 4][n]);
                uint32_t bl0 = __float_as_uint(Bs[b][1][q * 8 + tig][n]);
                uint32_t bl1 = __float_as_uint(Bs[b][1][q * 8 + tig + 4][n]);
#pragma unroll
                for (int mt = 0; mt < 2; ++mt) {
                    mma8(acc[mt][nt], ah[mt][0], ah[mt][1], ah[mt][2], ah[mt][3], bh0, bh1);
                    mma8(acc[mt][nt], al[mt][0], al[mt][1], al[mt][2], al[mt][3], bh0, bh1);
                    mma8(acc[mt][nt], ah[mt][0], ah[mt][1], ah[mt][2], ah[mt][3], bl0, bl1);
                }
            }
        }
        __syncthreads();
    }

    // epilogue: D rows grp/grp+8 per m-tile, cols 2*tig,2*tig+1 per n-tile
#pragma unroll
    for (int mt = 0; mt < 2; ++mt) {
#pragma unroll
        for (int nt = 0; nt < 4; ++nt) {
            int row = rbase + mt * 16 + grp;
            int col = cbase + nt * 8 + 2 * tig;
            *(float2*)(out + (size_t)row * FDIM + col) =
                make_float2(acc[mt][nt][0], acc[mt][nt][1]);
            *(float2*)(out + (size_t)(row + 8) * FDIM + col) =
                make_float2(acc[mt][nt][2], acc[mt][nt][3]);
        }
    }
}

// ---------------------------------------------------------------------------
extern "C" void kernel_launch(void* const* d_in, const int* in_sizes, int n_in,
                              void* d_out, int out_size) {
    const float* nodes = (const float*)d_in[0];   // [2,16384,64] f32
    const int*   nlist = (const int*)  d_in[1];   // [2,16384,32] i32
    const float* edges = (const float*)d_in[2];   // [2,16384,32,16] f32
    const float* w     = (const float*)d_in[3];   // [64,64,16] f32
    float* out = (float*)d_out;                   // [2,16384,64] f32

    perm_w_kernel<<<(KDIM * FDIM) / 256, 256>>>(w);
    round_wlo_kernel<<<(KDIM * FDIM) / 256, 256>>>();
    stage1_kernel<<<NODES / 8, 256>>>(nodes, nlist, edges);
    gemm_mma_kernel<<<NODES / 128, 256>>>(out);
}

// round 4
// speedup vs baseline: 1.8712x; 1.2624x over previous
#include <cuda_runtime.h>
#include <cstdint>

// Problem constants (fixed shapes)
#define NODES 32768       // B*N
#define NPB   16384       // nodes per batch
#define FDIM  64          // node feature dim (F)
#define EDIM  16          // edge feature dim (E)
#define KNB   32          // neighbors per node (K)
#define KDIM  1024        // F*E, GEMM reduction dim
#define KCH   32          // GEMM k-chunk
#define NC    (KDIM / KCH)

// Scratch (allocation-free rule: __device__ globals)
__device__ __align__(128) float g_T[(size_t)NODES * KDIM];   // 128 MB: T[node][k=l*16+n]
// W pre-packed in bf16 MMA-fragment order:
// [c(32)][q(2)][spl(2)][nt(8)][lane(32)][2 x u32]  (u32 = bf16x2 pair over k)
__device__ __align__(128) uint2 g_Wp[NC * 2 * 2 * 8 * 32];   // 256 KB

typedef unsigned long long u64;

// ---------------- f32x2 helpers (stage 1) ----------------
__device__ __forceinline__ u64 pack2(float lo, float hi) {
    u64 r; asm("mov.b64 %0, {%1, %2};" : "=l"(r) : "f"(lo), "f"(hi)); return r;
}
__device__ __forceinline__ u64 ffma2(u64 a, u64 b, u64 c) {
    u64 d; asm("fma.rn.f32x2 %0, %1, %2, %3;" : "=l"(d) : "l"(a), "l"(b), "l"(c)); return d;
}

// ---------------- bf16 / mma helpers ----------------
// pack two f32 -> bf16x2:  low half = e (even k), high half = o (odd k)
__device__ __forceinline__ uint32_t packbf(float o, float e) {
    uint32_t r; asm("cvt.rn.bf16x2.f32 %0, %1, %2;" : "=r"(r) : "f"(o), "f"(e)); return r;
}
// split float2 (even,odd) into bf16x2 hi + bf16x2 lo
__device__ __forceinline__ void split_bf16(float2 v, uint32_t& h, uint32_t& l) {
    uint32_t hh = packbf(v.y, v.x);
    float hx = __uint_as_float(hh << 16);
    float hy = __uint_as_float(hh & 0xffff0000u);
    l = packbf(v.y - hy, v.x - hx);
    h = hh;
}
__device__ __forceinline__ uint32_t smem_u32(const void* p) {
    uint32_t a;
    asm("{ .reg .u64 t; cvta.to.shared.u64 t, %1; cvt.u32.u64 %0, t; }" : "=r"(a) : "l"(p));
    return a;
}
__device__ __forceinline__ void cp_async16(uint32_t dst, const void* src) {
    asm volatile("cp.async.ca.shared.global [%0], [%1], 16;" :: "r"(dst), "l"(src) : "memory");
}
__device__ __forceinline__ void cp_commit() {
    asm volatile("cp.async.commit_group;" ::: "memory");
}
__device__ __forceinline__ void cp_wait1() {
    asm volatile("cp.async.wait_group 1;" ::: "memory");
}
__device__ __forceinline__ void cp_wait0() {
    asm volatile("cp.async.wait_group 0;" ::: "memory");
}
// m16n8k16 bf16 mma, accumulate in place
__device__ __forceinline__ void mma16(float* c, const uint32_t* a, uint32_t b0, uint32_t b1) {
    asm volatile(
        "mma.sync.aligned.m16n8k16.row.col.f32.bf16.bf16.f32 "
        "{%0,%1,%2,%3}, {%4,%5,%6,%7}, {%8,%9}, {%0,%1,%2,%3};"
        : "+f"(c[0]), "+f"(c[1]), "+f"(c[2]), "+f"(c[3])
        : "r"(a[0]), "r"(a[1]), "r"(a[2]), "r"(a[3]), "r"(b0), "r"(b1));
}

// ---------------------------------------------------------------------------
// Kernel 0: pack W into bf16 hi/lo MMA-fragment order, scale by 1/K.
// One thread per (c,q,nt,lane): produces b0/b1 pairs for hi and lo splits.
// W'[k=l*16+n'][m] = w[l][m][n'] / 32,  m = output col.
// ---------------------------------------------------------------------------
__global__ __launch_bounds__(256) void pack_w_kernel(const float* __restrict__ w) {
    int idx  = blockIdx.x * blockDim.x + threadIdx.x;   // 0..16383
    int lane = idx & 31;
    int nt   = (idx >> 5) & 7;
    int q    = (idx >> 8) & 1;
    int c    = idx >> 9;
    int tig  = lane & 3;
    int grp  = lane >> 2;
    int m    = nt * 8 + grp;
    int k0   = c * KCH + q * 16 + 2 * tig;

    float v[4];   // k0, k0+1, k0+8, k0+9
#pragma unroll
    for (int s = 0; s < 4; ++s) {
        int k = k0 + (s >> 1) * 8 + (s & 1);
        int l = k >> 4, n = k & 15;
        v[s] = w[l * (FDIM * EDIM) + m * EDIM + n] * 0.03125f;
    }
    uint32_t b0h = packbf(v[1], v[0]);
    uint32_t b1h = packbf(v[3], v[2]);
    uint32_t b0l = packbf(v[1] - __uint_as_float(b0h & 0xffff0000u),
                          v[0] - __uint_as_float(b0h << 16));
    uint32_t b1l = packbf(v[3] - __uint_as_float(b1h & 0xffff0000u),
                          v[2] - __uint_as_float(b1h << 16));
    // layout: (((c*2+q)*2+spl)*8+nt)*32 + lane
    int base = ((c * 2 + q) * 2) * 8 + nt;
    g_Wp[(size_t)base * 32 + lane]        = make_uint2(b0h, b1h);   // spl=0 (hi)
    g_Wp[(size_t)(base + 8) * 32 + lane]  = make_uint2(b0l, b1l);   // spl=1 (lo)
}

// ---------------------------------------------------------------------------
// Kernel 1: stage 1 — gather neighbors + rank-32 outer product per node.
// One warp per node; depth-8 software pipeline on the gather. (unchanged)
// ---------------------------------------------------------------------------
__global__ __launch_bounds__(256) void stage1_kernel(
    const float* __restrict__ nodes,
    const int*   __restrict__ nlist,
    const float* __restrict__ edges)
{
    __shared__ float se[8][512];

    const int warp = threadIdx.x >> 5;
    const int lane = threadIdx.x & 31;
    const int node = (blockIdx.x << 3) + warp;
    const int b    = node >> 14;
    const float* nbase = nodes + (size_t)b * NPB * FDIM;

    const float4* e4 = (const float4*)(edges + (size_t)node * (KNB * EDIM));
    float4* s4 = (float4*)se[warp];
    s4[lane]       = e4[lane];
    s4[lane + 32]  = e4[lane + 32];
    s4[lane + 64]  = e4[lane + 64];
    s4[lane + 96]  = e4[lane + 96];
    int idx = nlist[node * KNB + lane];
    __syncwarp();

    u64 T0[8], T1[8];
#pragma unroll
    for (int p = 0; p < 8; ++p) { T0[p] = 0ull; T1[p] = 0ull; }

    float2 xq[8];
#pragma unroll
    for (int j = 0; j < 8; ++j) {
        int nb = __shfl_sync(0xffffffffu, idx, j);
        xq[j] = *(const float2*)(nbase + (size_t)nb * FDIM + 2 * lane);
    }

#pragma unroll
    for (int j = 0; j < KNB; ++j) {
        float2 xc = xq[j & 7];
        if (j + 8 < KNB) {
            int nb = __shfl_sync(0xffffffffu, idx, j + 8);
            xq[j & 7] = *(const float2*)(nbase + (size_t)nb * FDIM + 2 * lane);
        }
        u64 xx0 = pack2(xc.x, xc.x);
        u64 xx1 = pack2(xc.y, xc.y);
        const ulonglong2* ep = (const ulonglong2*)&se[warp][j * EDIM];
        ulonglong2 e01 = ep[0];
        ulonglong2 e23 = ep[1];
        ulonglong2 e45 = ep[2];
        ulonglong2 e67 = ep[3];
        T0[0] = ffma2(xx0, e01.x, T0[0]);  T0[1] = ffma2(xx0, e01.y, T0[1]);
        T0[2] = ffma2(xx0, e23.x, T0[2]);  T0[3] = ffma2(xx0, e23.y, T0[3]);
        T0[4] = ffma2(xx0, e45.x, T0[4]);  T0[5] = ffma2(xx0, e45.y, T0[5]);
        T0[6] = ffma2(xx0, e67.x, T0[6]);  T0[7] = ffma2(xx0, e67.y, T0[7]);
        T1[0] = ffma2(xx1, e01.x, T1[0]);  T1[1] = ffma2(xx1, e01.y, T1[1]);
        T1[2] = ffma2(xx1, e23.x, T1[2]);  T1[3] = ffma2(xx1, e23.y, T1[3]);
        T1[4] = ffma2(xx1, e45.x, T1[4]);  T1[5] = ffma2(xx1, e45.y, T1[5]);
        T1[6] = ffma2(xx1, e67.x, T1[6]);  T1[7] = ffma2(xx1, e67.y, T1[7]);
    }

    ulonglong2* tp = (ulonglong2*)(g_T + (size_t)node * KDIM + lane * 32);
#pragma unroll
    for (int p = 0; p < 4; ++p) tp[p]     = make_ulonglong2(T0[2*p], T0[2*p+1]);
#pragma unroll
    for (int p = 0; p < 4; ++p) tp[4 + p] = make_ulonglong2(T1[2*p], T1[2*p+1]);
}

// ---------------------------------------------------------------------------
// Kernel 2: bf16 mma.sync GEMM, 3-split fp32 emulation (AhBh + AlBh + AhBl).
// out[32768,64] = g_T[32768,1024] @ W'[1024,64]
// CTA: 128 rows x 64 cols, 4 warps, warp = 32 rows x 64 cols (2 mt x 8 nt).
// A: cp.async fp32 -> smem(pad 40) -> LDS.64 -> bf16 split in regs.
// B: pre-packed frag order, cp.async -> contiguous LDS.64.
// ---------------------------------------------------------------------------
#define A_STRIDE 40                        // floats per row (bank-conflict-free)
#define A_BUF    (128 * A_STRIDE)          // floats per buffer (5120)
#define B_BUF    2048                      // u32 per buffer (8 KB)
#define GEMM_SMEM (2 * A_BUF * 4 + 2 * B_BUF * 4)   // 57344 B

__global__ __launch_bounds__(128, 2) void gemm_bf16_kernel(float* __restrict__ out)
{
    extern __shared__ char smraw[];
    float*    As = (float*)smraw;                       // [2][128][40]
    uint32_t* Bs = (uint32_t*)(smraw + 2 * A_BUF * 4);  // [2][2048]

    const int tid  = threadIdx.x;
    const int lane = tid & 31;
    const int wid  = tid >> 5;          // 0..3
    const int tig  = lane & 3;
    const int grp  = lane >> 2;
    const int rbase = blockIdx.x * 128;
    const int wrow  = wid * 32;

    const float* aSrc = g_T + (size_t)(rbase + tid) * KDIM;   // one row per thread
    const char*  bSrc = (const char*)g_Wp;

    float acc[2][8][4];
#pragma unroll
    for (int mt = 0; mt < 2; ++mt)
#pragma unroll
        for (int nt = 0; nt < 8; ++nt)
#pragma unroll
            for (int r = 0; r < 4; ++r) acc[mt][nt][r] = 0.0f;

    // ---- staging lambda (manual) ----
    // A: thread copies its whole row chunk (8 x 16B, contiguous in gmem)
    // B: thread copies 64 B of the pre-packed chunk
#define STAGE(c, buf)                                                          \
    do {                                                                       \
        uint32_t ad = smem_u32(As + (buf) * A_BUF + tid * A_STRIDE);           \
        const float* as_ = aSrc + (c) * KCH;                                   \
        _Pragma("unroll")                                                      \
        for (int i = 0; i < 8; ++i) cp_async16(ad + i * 16, as_ + i * 4);      \
        uint32_t bd = smem_u32(Bs + (buf) * B_BUF) + tid * 64;                 \
        const char* bs_ = bSrc + (size_t)(c) * 8192 + tid * 64;                \
        _Pragma("unroll")                                                      \
        for (int i = 0; i < 4; ++i) cp_async16(bd + i * 16, bs_ + i * 16);     \
        cp_commit();                                                           \
    } while (0)

    STAGE(0, 0);

    for (int c = 0; c < NC; ++c) {
        const int buf = c & 1;
        if (c + 1 < NC) { STAGE(c + 1, buf ^ 1); cp_wait1(); }
        else            { cp_wait0(); }
        __syncthreads();

        const float*    Ab = As + buf * A_BUF;
        const uint32_t* Bb = Bs + buf * B_BUF;

#pragma unroll
        for (int q = 0; q < 2; ++q) {
            uint32_t ah[2][4], al[2][4];
#pragma unroll
            for (int mt = 0; mt < 2; ++mt) {
                const float* pr = Ab + (wrow + mt * 16 + grp) * A_STRIDE + q * 16 + 2 * tig;
                float2 v0 = *(const float2*)(pr);
                float2 v1 = *(const float2*)(pr + 8 * A_STRIDE);
                float2 v2 = *(const float2*)(pr + 8);
                float2 v3 = *(const float2*)(pr + 8 * A_STRIDE + 8);
                split_bf16(v0, ah[mt][0], al[mt][0]);
                split_bf16(v1, ah[mt][1], al[mt][1]);
                split_bf16(v2, ah[mt][2], al[mt][2]);
                split_bf16(v3, ah[mt][3], al[mt][3]);
            }
#pragma unroll
            for (int nt = 0; nt < 8; ++nt) {
                uint2 bh = *(const uint2*)(Bb + ((q * 2 + 0) * 8 + nt) * 64 + lane * 2);
                uint2 bl = *(const uint2*)(Bb + ((q * 2 + 1) * 8 + nt) * 64 + lane * 2);
#pragma unroll
                for (int mt = 0; mt < 2; ++mt) {
                    mma16(acc[mt][nt], ah[mt], bh.x, bh.y);
                    mma16(acc[mt][nt], al[mt], bh.x, bh.y);
                    mma16(acc[mt][nt], ah[mt], bl.x, bl.y);
                }
            }
        }
        __syncthreads();
    }

    // epilogue
#pragma unroll
    for (int mt = 0; mt < 2; ++mt) {
#pragma unroll
        for (int nt = 0; nt < 8; ++nt) {
            int row = rbase + wrow + mt * 16 + grp;
            int col = nt * 8 + 2 * tig;
            *(float2*)(out + (size_t)row * FDIM + col) =
                make_float2(acc[mt][nt][0], acc[mt][nt][1]);
            *(float2*)(out + (size_t)(row + 8) * FDIM + col) =
                make_float2(acc[mt][nt][2], acc[mt][nt][3]);
        }
    }
#undef STAGE
}

// ---------------------------------------------------------------------------
extern "C" void kernel_launch(void* const* d_in, const int* in_sizes, int n_in,
                              void* d_out, int out_size) {
    const float* nodes = (const float*)d_in[0];   // [2,16384,64] f32
    const int*   nlist = (const int*)  d_in[1];   // [2,16384,32] i32
    const float* edges = (const float*)d_in[2];   // [2,16384,32,16] f32
    const float* w     = (const float*)d_in[3];   // [64,64,16] f32
    float* out = (float*)d_out;                   // [2,16384,64] f32

    cudaFuncSetAttribute(gemm_bf16_kernel,
                         cudaFuncAttributeMaxDynamicSharedMemorySize, GEMM_SMEM);

    pack_w_kernel<<<64, 256>>>(w);
    stage1_kernel<<<NODES / 8, 256>>>(nodes, nlist, edges);
    gemm_bf16_kernel<<<NODES / 128, 128, GEMM_SMEM>>>(out);
}